// round 13
// baseline (speedup 1.0000x reference)
#include <cuda_runtime.h>
#include <cuda_fp16.h>
#include <math.h>
#include <stdint.h>

#define BB 4
#define NN 1024
#define CC 1024
#define HH 16
#define DH 64
#define MROWS (BB*NN)   // 4096

// ---------------- scratch (device globals; no allocation allowed) ----------
__device__ __half g_lga[BB*NN*NN];    // logits partial (K 0..511),  8 MB
__device__ __half g_lgb[BB*NN*NN];    // logits partial (K 512..1023)
__device__ __half g_x16[MROWS*CC];
__device__ __half g_pre[MROWS*CC];
__device__ __half g_ctx[MROWS*CC];
__device__ __half g_q16[BB*HH*NN*DH];
__device__ __half g_k16[BB*HH*NN*DH];
__device__ __half g_v16[BB*HH*NN*DH];
__device__ __half g_wpre[CC*CC];
__device__ __half g_wq[CC*CC];
__device__ __half g_wk[CC*CC];
__device__ __half g_wv[CC*CC];
__device__ __half g_wp[CC*CC];

// ======================= portable PTX helpers ==============================
__device__ __forceinline__ uint32_t smem_to_u32(const void* p) {
    uint32_t a;
    asm("{ .reg .u64 t; cvta.to.shared.u64 t, %1; cvt.u32.u64 %0, t; }"
        : "=r"(a) : "l"(p));
    return a;
}
#define CP_ASYNC16(dst, src) \
    asm volatile("cp.async.cg.shared.global [%0], [%1], 16;" \
                 :: "r"(dst), "l"(src) : "memory")
#define CP_COMMIT() asm volatile("cp.async.commit_group;" ::: "memory")
#define CP_WAIT0()  asm volatile("cp.async.wait_group 0;" ::: "memory")

__device__ __forceinline__ void ldsm4(uint32_t* r, uint32_t addr) {
    asm volatile("ldmatrix.sync.aligned.m8n8.x4.shared.b16 {%0,%1,%2,%3}, [%4];"
        : "=r"(r[0]), "=r"(r[1]), "=r"(r[2]), "=r"(r[3]) : "r"(addr));
}
__device__ __forceinline__ void ldsm4t(uint32_t* r, uint32_t addr) {
    asm volatile("ldmatrix.sync.aligned.m8n8.x4.trans.shared.b16 {%0,%1,%2,%3}, [%4];"
        : "=r"(r[0]), "=r"(r[1]), "=r"(r[2]), "=r"(r[3]) : "r"(addr));
}
__device__ __forceinline__ void mma16816(float* c, const uint32_t* a,
                                         const uint32_t* b) {
    asm volatile("mma.sync.aligned.m16n8k16.row.col.f32.f16.f16.f32 "
        "{%0,%1,%2,%3}, {%4,%5,%6,%7}, {%8,%9}, {%0,%1,%2,%3};"
        : "+f"(c[0]), "+f"(c[1]), "+f"(c[2]), "+f"(c[3])
        : "r"(a[0]), "r"(a[1]), "r"(a[2]), "r"(a[3]), "r"(b[0]), "r"(b[1]));
}
__device__ __forceinline__ uint32_t pack_h2(float x, float y) {
    __half2 p = __floats2half2_rn(x, y);
    return *(uint32_t*)&p;
}

// ======================= prep kernels ======================================
__global__ __launch_bounds__(256) void round2h(
    const float2* __restrict__ in, __half2* __restrict__ o, int n2)
{
    int i = blockIdx.x * blockDim.x + threadIdx.x;
    if (i < n2) {
        float2 a = in[i];
        o[i] = __floats2half2_rn(a.x, a.y);
    }
}

__global__ __launch_bounds__(256) void wround_T5(
    const float* __restrict__ W0, const float* __restrict__ W1,
    const float* __restrict__ W2, const float* __restrict__ W3,
    const float* __restrict__ W4,
    __half* o0, __half* o1, __half* o2, __half* o3, __half* o4)
{
    const float* Ws[5] = {W0, W1, W2, W3, W4};
    __half* Os[5] = {o0, o1, o2, o3, o4};
    const int z = blockIdx.z;
    const float* W = Ws[z];
    __half* th = Os[z];

    __shared__ float s[32][33];
    const int tx = threadIdx.x, ty = threadIdx.y;
    const int n0 = blockIdx.x * 32, k0 = blockIdx.y * 32;
#pragma unroll
    for (int i = ty; i < 32; i += 8)
        s[i][tx] = W[(size_t)(k0 + i) * CC + n0 + tx];
    __syncthreads();
#pragma unroll
    for (int i = ty; i < 32; i += 8)
        th[(size_t)(n0 + i) * CC + k0 + tx] = __float2half(s[tx][i]);
}

// ======================= HMMA GEMM common machinery ========================
enum { EPI_LOGITS = 2, EPI_RESID = 3 };

#define OFF_A 0
#define OFF_B 8192
#define STAGE_BYTES 16384
#define SMEM_HMMA (2 * STAGE_BYTES)    // 32768 -> 2 CTAs/SM

struct GemmCore {
    uint32_t smem_u32;
    int lane, wid, wr, wc, lrow, lc, rowSel, hiH, rmod;
    __device__ __forceinline__ void init(uint32_t smem, int t) {
        smem_u32 = smem;
        lane = t & 31; wid = t >> 5;
        wr = wid & 1; wc = wid >> 1;
        lrow = t >> 2; lc = t & 3;
        rowSel = lane & 15; hiH = lane >> 4; rmod = (rowSel >> 1) & 3;
    }
    __device__ __forceinline__ void load_stage(
        const __half* Ab, const __half* Bb,
        int row0, int col0, int ch, int s) const
    {
        const size_t kb = (size_t)ch * 32 + lc * 8;
        const uint32_t sb = smem_u32 + s * STAGE_BYTES;
#pragma unroll
        for (int i = 0; i < 2; i++) {
            const int r = lrow + i * 64;
            const uint32_t so = (uint32_t)(r * 64 + ((lc ^ ((r >> 1) & 3)) * 16));
            CP_ASYNC16(sb + OFF_A + so, Ab + (size_t)(row0 + r) * CC + kb);
            CP_ASYNC16(sb + OFF_B + so, Bb + (size_t)(col0 + r) * CC + kb);
        }
    }
    // mainloop over [kch0, kch0+nch) chunks of K=32
    __device__ __forceinline__ void run(
        const __half* Ab, const __half* Bb,
        int row0, int col0, int kch0, int nch, float acc[4][4][4]) const
    {
#pragma unroll
        for (int a = 0; a < 4; a++)
#pragma unroll
            for (int b = 0; b < 4; b++)
#pragma unroll
                for (int c = 0; c < 4; c++) acc[a][b][c] = 0.0f;

        load_stage(Ab, Bb, row0, col0, kch0, 0);
        CP_COMMIT();
        for (int ch = 0; ch < nch; ch++) {
            CP_WAIT0();
            __syncthreads();
            if (ch < nch - 1) {
                load_stage(Ab, Bb, row0, col0, kch0 + ch + 1, (ch + 1) & 1);
                CP_COMMIT();
            }

            const uint32_t sb = smem_u32 + (ch & 1) * STAGE_BYTES;
#pragma unroll
            for (int k16 = 0; k16 < 2; k16++) {
                const int chunk = k16 * 2 + hiH;
                uint32_t bh[4][2];
#pragma unroll
                for (int n16 = 0; n16 < 2; n16++) {
                    const int row = wc * 32 + n16 * 16 + rowSel;
                    const uint32_t off = (uint32_t)(row * 64 + ((chunk ^ rmod) * 16));
                    uint32_t rh[4];
                    ldsm4(rh, sb + OFF_B + off);
                    bh[n16 * 2][0] = rh[0]; bh[n16 * 2 + 1][0] = rh[1];
                    bh[n16 * 2][1] = rh[2]; bh[n16 * 2 + 1][1] = rh[3];
                }
#pragma unroll
                for (int mt = 0; mt < 4; mt++) {
                    const int row = wr * 64 + mt * 16 + rowSel;
                    const uint32_t off = (uint32_t)(row * 64 + ((chunk ^ rmod) * 16));
                    uint32_t ah[4];
                    ldsm4(ah, sb + OFF_A + off);
#pragma unroll
                    for (int nt = 0; nt < 4; nt++) mma16816(acc[mt][nt], ah, bh[nt]);
                }
            }
        }
    }
};

// ---- merged pre/Q/K/V GEMM ------------------------------------------------
__global__ __launch_bounds__(256, 2) void hmma_qkv(
    const __half* __restrict__ x16,
    const __half* wpre, const __half* wq, const __half* wk, const __half* wv,
    const float* __restrict__ bpre,
    __half* pre, __half* q16, __half* k16, __half* v16)
{
    extern __shared__ char smem_raw[];
    GemmCore gc_;
    gc_.init(smem_to_u32(smem_raw), threadIdx.x);

    const int g    = blockIdx.x >> 3;
    const int col0 = (blockIdx.x & 7) * 128;
    const int row0 = blockIdx.y * 128;

    const __half* Bp[4] = {wpre, wq, wk, wv};
    __half* Op[4] = {pre, q16, k16, v16};

    float acc[4][4][4];
    gc_.run(x16, Bp[g], row0, col0, 0, 32, acc);

    const int r0g = row0 + gc_.wr * 64 + (gc_.lane >> 2);
    const int c0g = col0 + gc_.wc * 32 + (gc_.lane & 3) * 2;
#pragma unroll
    for (int mt = 0; mt < 4; mt++) {
#pragma unroll
        for (int nt = 0; nt < 4; nt++) {
            const int gcc = c0g + nt * 8;
#pragma unroll
            for (int half = 0; half < 2; half++) {
                const int gr = r0g + mt * 16 + half * 8;
                float v0 = acc[mt][nt][half * 2 + 0];
                float v1 = acc[mt][nt][half * 2 + 1];
                if (g == 0) {
                    v0 += bpre[gcc]; v1 += bpre[gcc + 1];
                    v0 = v0 / (1.0f + __expf(-v0));
                    v1 = v1 / (1.0f + __expf(-v1));
                    *(__half2*)(Op[0] + (size_t)gr * CC + gcc) =
                        __floats2half2_rn(v0, v1);
                } else {
                    const int b = gr >> 10, n = gr & (NN - 1);
                    const int h = gcc >> 6, dh = gcc & 63;
                    const size_t o = ((size_t)(b * HH + h) * NN + n) * DH + dh;
                    *(__half2*)(Op[g] + o) = __floats2half2_rn(v0, v1);
                }
            }
        }
    }
}

// ---- logits (split-K x2, symmetric upper-tri, fp16 partials) + proj -------
__global__ __launch_bounds__(256, 2) void hmma_gemm(
    const __half* __restrict__ As, const __half* __restrict__ Bs,
    const float* __restrict__ bias, const float* __restrict__ resid,
    float* __restrict__ outF, __half* __restrict__ outHa,
    __half* __restrict__ outHb, int mode)
{
    extern __shared__ char smem_raw[];
    GemmCore gc_;
    gc_.init(smem_to_u32(smem_raw), threadIdx.x);

    int row0, col0, ti = 0, tj = 0, kch0 = 0, nch = 32;
    const __half *Ab, *Bb;
    __half* outH = nullptr;
    if (mode == EPI_LOGITS) {
        int li = blockIdx.x, rem = 8;
        while (li >= rem) { li -= rem; rem--; ti++; }
        tj = ti + li;
        row0 = ti * 128; col0 = tj * 128;
        const int batch = blockIdx.z >> 1;
        const int kh    = blockIdx.z & 1;
        kch0 = kh * 16; nch = 16;
        Ab = As + (size_t)batch * NN * CC;
        Bb = Ab;
        outH = (kh ? outHb : outHa) + (size_t)batch * NN * NN;
    } else {
        row0 = blockIdx.y * 128;
        col0 = blockIdx.x * 128;
        Ab = As; Bb = Bs;
    }

    float acc[4][4][4];
    gc_.run(Ab, Bb, row0, col0, kch0, nch, acc);

    const int r0g = row0 + gc_.wr * 64 + (gc_.lane >> 2);
    const int c0g = col0 + gc_.wc * 32 + (gc_.lane & 3) * 2;
#pragma unroll
    for (int mt = 0; mt < 4; mt++) {
#pragma unroll
        for (int nt = 0; nt < 4; nt++) {
            const int gcc = c0g + nt * 8;
#pragma unroll
            for (int half = 0; half < 2; half++) {
                const int gr = r0g + mt * 16 + half * 8;
                float v0 = acc[mt][nt][half * 2 + 0];
                float v1 = acc[mt][nt][half * 2 + 1];
                if (mode == EPI_LOGITS) {
                    v0 *= 0.03125f; v1 *= 0.03125f;
                    __half h0 = __float2half(v0), h1 = __float2half(v1);
                    outH[(size_t)gr * NN + gcc]     = h0;
                    outH[(size_t)gr * NN + gcc + 1] = h1;
                    if (ti != tj) {
                        outH[(size_t)gcc * NN + gr]       = h0;
                        outH[(size_t)(gcc + 1) * NN + gr] = h1;
                    }
                } else { // EPI_RESID
                    const size_t ro = (size_t)gr * CC + gcc;
                    outF[ro]     = v0 + bias[gcc]     + resid[ro];
                    outF[ro + 1] = v1 + bias[gcc + 1] + resid[ro + 1];
                }
            }
        }
    }
}

// ======================= HMMA flash attention (128-q tile) =================
#define SMQ 0
#define KVBASE 16384
#define KVST 16384
#define KV_K 0
#define KV_V 8192
#define SMEM_FATT (KVBASE + 2 * KVST)    // 49152

__global__ __launch_bounds__(256, 2) void fattn(
    const __half* __restrict__ q16, const __half* __restrict__ k16,
    const __half* __restrict__ v16,
    const __half* __restrict__ lga, const __half* __restrict__ lgb,
    const float* __restrict__ pi_p, __half* __restrict__ ctx)
{
    extern __shared__ char sm[];
    const uint32_t sb = smem_to_u32(sm);
    const int t = threadIdx.x, lane = t & 31, w = t >> 5;
    const int bh = blockIdx.y, b = bh >> 4, h = bh & 15;
    const int q0 = blockIdx.x * 128;
    const size_t hoff = (size_t)bh * NN * DH;
    const float pi = pi_p[0];

#pragma unroll
    for (int i = 0; i < 4; i++) {
        const int id = t + i * 256;
        const int r = id >> 3, c = id & 7;
        const uint32_t off = (uint32_t)(r * 128 + ((c ^ (r & 7)) * 16));
        CP_ASYNC16(sb + SMQ + off, q16 + hoff + (size_t)(q0 + r) * DH + c * 8);
    }
    CP_COMMIT();

    auto load_kv = [&](int kt, int buf) {
        const uint32_t kvb = sb + KVBASE + buf * KVST;
#pragma unroll
        for (int i = 0; i < 2; i++) {
            const int id = t + i * 256;
            const int r = id >> 3, c = id & 7;
            const uint32_t off = (uint32_t)(r * 128 + ((c ^ (r & 7)) * 16));
            const size_t g = hoff + (size_t)(kt * 64 + r) * DH + c * 8;
            CP_ASYNC16(kvb + KV_K + off, k16 + g);
            CP_ASYNC16(kvb + KV_V + off, v16 + g);
        }
    };

    load_kv(0, 0);
    CP_COMMIT();

    float S[8][4], O[8][4];
#pragma unroll
    for (int j = 0; j < 8; j++)
#pragma unroll
        for (int c = 0; c < 4; c++) O[j][c] = 0.0f;
    float m0 = -1e30f, m1 = -1e30f, l0 = 0.0f, l1 = 0.0f;

    const int qr = w * 16 + (lane >> 2);
    const size_t lgro = (size_t)b * NN * NN + (size_t)(q0 + qr) * NN;
    const __half* la = lga + lgro;
    const __half* lb = lgb + lgro;
    const int rowSel = lane & 15, hiH = lane >> 4;

    for (int kt = 0; kt < 16; kt++) {
        const int mk = kt * 64;
        CP_WAIT0();
        __syncthreads();
        if (kt < 15) { load_kv(kt + 1, (kt + 1) & 1); CP_COMMIT(); }

        const uint32_t kvb = sb + KVBASE + (kt & 1) * KVST;

        // ---- S = Q K^T ----
#pragma unroll
        for (int j = 0; j < 8; j++)
#pragma unroll
            for (int c = 0; c < 4; c++) S[j][c] = 0.0f;

#pragma unroll
        for (int kc = 0; kc < 4; kc++) {
            const int chunk = 2 * kc + hiH;
            uint32_t aq[4];
            {
                const int row = w * 16 + rowSel;
                const uint32_t off = (uint32_t)(row * 128 + ((chunk ^ (row & 7)) * 16));
                ldsm4(aq, sb + SMQ + off);
            }
#pragma unroll
            for (int j16 = 0; j16 < 4; j16++) {
                const int row = j16 * 16 + rowSel;
                const uint32_t off = (uint32_t)(row * 128 + ((chunk ^ (row & 7)) * 16));
                uint32_t rh[4];
                ldsm4(rh, kvb + KV_K + off);
                uint32_t b0[2] = {rh[0], rh[2]}, b1[2] = {rh[1], rh[3]};
                mma16816(S[2 * j16],     aq, b0);
                mma16816(S[2 * j16 + 1], aq, b1);
            }
        }

        // ---- bias (two fp16 partials) + online softmax ----
        float mx0 = -1e30f, mx1 = -1e30f;
#pragma unroll
        for (int j = 0; j < 8; j++) {
            const int cix = mk + j * 8 + (lane & 3) * 2;
            float2 a0 = __half22float2(*(const __half2*)(la + cix));
            float2 b0v = __half22float2(*(const __half2*)(lb + cix));
            float2 a1 = __half22float2(*(const __half2*)(la + 8 * NN + cix));
            float2 b1v = __half22float2(*(const __half2*)(lb + 8 * NN + cix));
            S[j][0] = S[j][0] * 0.125f + pi * (a0.x + b0v.x);
            S[j][1] = S[j][1] * 0.125f + pi * (a0.y + b0v.y);
            S[j][2] = S[j][2] * 0.125f + pi * (a1.x + b1v.x);
            S[j][3] = S[j][3] * 0.125f + pi * (a1.y + b1v.y);
            mx0 = fmaxf(mx0, fmaxf(S[j][0], S[j][1]));
            mx1 = fmaxf(mx1, fmaxf(S[j][2], S[j][3]));
        }
        mx0 = fmaxf(mx0, __shfl_xor_sync(0xffffffffu, mx0, 1));
        mx0 = fmaxf(mx0, __shfl_xor_sync(0xffffffffu, mx0, 2));
        mx1 = fmaxf(mx1, __shfl_xor_sync(0xffffffffu, mx1, 1));
        mx1 = fmaxf(mx1, __shfl_xor_sync(0xffffffffu, mx1, 2));
        const float mn0 = fmaxf(m0, mx0), mn1 = fmaxf(m1, mx1);
        const float a0s = __expf(m0 - mn0), a1s = __expf(m1 - mn1);
        m0 = mn0; m1 = mn1;
        float s0 = 0.0f, s1 = 0.0f;
#pragma unroll
        for (int j = 0; j < 8; j++) {
            S[j][0] = __expf(S[j][0] - mn0); S[j][1] = __expf(S[j][1] - mn0);
            S[j][2] = __expf(S[j][2] - mn1); S[j][3] = __expf(S[j][3] - mn1);
            s0 += S[j][0] + S[j][1];
            s1 += S[j][2] + S[j][3];
        }
        s0 += __shfl_xor_sync(0xffffffffu, s0, 1);
        s0 += __shfl_xor_sync(0xffffffffu, s0, 2);
        s1 += __shfl_xor_sync(0xffffffffu, s1, 1);
        s1 += __shfl_xor_sync(0xffffffffu, s1, 2);
        l0 = l0 * a0s + s0; l1 = l1 * a1s + s1;
#pragma unroll
        for (int j = 0; j < 8; j++) {
            O[j][0] *= a0s; O[j][1] *= a0s; O[j][2] *= a1s; O[j][3] *= a1s;
        }

        // ---- O += P V ----
#pragma unroll
        for (int kc = 0; kc < 4; kc++) {
            uint32_t ph[4];
#pragma unroll
            for (int half = 0; half < 2; half++) {
                const int j = 2 * kc + half;
                ph[half * 2 + 0] = pack_h2(S[j][0], S[j][1]);
                ph[half * 2 + 1] = pack_h2(S[j][2], S[j][3]);
            }
#pragma unroll
            for (int jc = 0; jc < 4; jc++) {
                const int row = kc * 16 + rowSel;
                const int chunk = 2 * jc + hiH;
                const uint32_t off = (uint32_t)(row * 128 + ((chunk ^ (row & 7)) * 16));
                uint32_t rv[4];
                ldsm4t(rv, kvb + KV_V + off);
                uint32_t v0[2] = {rv[0], rv[1]}, v1[2] = {rv[2], rv[3]};
                mma16816(O[2 * jc],     ph, v0);
                mma16816(O[2 * jc + 1], ph, v1);
            }
        }
    }

    // ---- epilogue ----
    const float inv0 = 1.0f / l0, inv1 = 1.0f / l1;
    const size_t r0o = (size_t)(b * NN + q0 + qr) * CC;
    const size_t r1o = r0o + (size_t)8 * CC;
    const int cb = h * DH + (lane & 3) * 2;
#pragma unroll
    for (int dj = 0; dj < 8; dj++) {
        const int col = cb + dj * 8;
        *(__half2*)(ctx + r0o + col) = __floats2half2_rn(O[dj][0] * inv0, O[dj][1] * inv0);
        *(__half2*)(ctx + r1o + col) = __floats2half2_rn(O[dj][2] * inv1, O[dj][3] * inv1);
    }
}

// ---------------------------------------------------------------------------
extern "C" void kernel_launch(void* const* d_in, const int* in_sizes, int n_in,
                              void* d_out, int out_size)
{
    (void)in_sizes; (void)n_in; (void)out_size;
    const float* x     = (const float*)d_in[0];
    const float* Wq    = (const float*)d_in[1];
    const float* Wk    = (const float*)d_in[2];
    const float* Wv    = (const float*)d_in[3];
    const float* Wproj = (const float*)d_in[4];
    const float* bproj = (const float*)d_in[5];
    const float* Wpre  = (const float*)d_in[6];
    const float* bpre  = (const float*)d_in[7];
    const float* pi    = (const float*)d_in[8];
    float* out = (float*)d_out;

    __half *lga, *lgb;
    __half *x16, *pre, *ctx, *q16, *k16, *v16;
    __half *wpre, *wq, *wk, *wv, *wp;
    cudaGetSymbolAddress((void**)&lga,  g_lga);
    cudaGetSymbolAddress((void**)&lgb,  g_lgb);
    cudaGetSymbolAddress((void**)&x16,  g_x16);
    cudaGetSymbolAddress((void**)&pre,  g_pre);
    cudaGetSymbolAddress((void**)&ctx,  g_ctx);
    cudaGetSymbolAddress((void**)&q16,  g_q16);
    cudaGetSymbolAddress((void**)&k16,  g_k16);
    cudaGetSymbolAddress((void**)&v16,  g_v16);
    cudaGetSymbolAddress((void**)&wpre, g_wpre);
    cudaGetSymbolAddress((void**)&wq,   g_wq);
    cudaGetSymbolAddress((void**)&wk,   g_wk);
    cudaGetSymbolAddress((void**)&wv,   g_wv);
    cudaGetSymbolAddress((void**)&wp,   g_wp);

    cudaFuncSetAttribute(hmma_qkv,  cudaFuncAttributeMaxDynamicSharedMemorySize, SMEM_HMMA);
    cudaFuncSetAttribute(hmma_gemm, cudaFuncAttributeMaxDynamicSharedMemorySize, SMEM_HMMA);
    cudaFuncSetAttribute(fattn,     cudaFuncAttributeMaxDynamicSharedMemorySize, SMEM_FATT);

    // ---- prep ----
    dim3 wst(32, 8), wsg(32, 32, 5);
    wround_T5<<<wsg, wst>>>(Wpre, Wq, Wk, Wv, Wproj, wpre, wq, wk, wv, wp);
    const int n2 = MROWS * CC / 2;
    round2h<<<(n2 + 255) / 256, 256>>>((const float2*)x, (__half2*)x16, n2);

    // ---- merged pre/Q/K/V GEMM ----
    dim3 mb(256);
    dim3 gqkv(32, MROWS / 128, 1);
    hmma_qkv<<<gqkv, mb, SMEM_HMMA>>>(x16, wpre, wq, wk, wv, bpre,
                                      pre, q16, k16, v16);

    // ---- logits GEMM: 36 upper-tri tiles x 4 batches x 2 K-halves = 288 ----
    dim3 glog(36, 1, BB * 2);
    hmma_gemm<<<glog, mb, SMEM_HMMA>>>(pre, pre, nullptr, nullptr,
                                       nullptr, lga, lgb, EPI_LOGITS);

    // ---- HMMA flash attention ----
    dim3 ga(NN / 128, BB * HH);
    fattn<<<ga, 256, SMEM_FATT>>>(q16, k16, v16, lga, lgb, pi, ctx);

    // ---- projection + residual ----
    dim3 gl(CC / 128, MROWS / 128, 1);
    hmma_gemm<<<gl, mb, SMEM_HMMA>>>(ctx, wp, bproj, x,
                                     out, nullptr, nullptr, EPI_RESID);
}

// round 14
// speedup vs baseline: 1.0976x; 1.0976x over previous
#include <cuda_runtime.h>
#include <cuda_fp16.h>
#include <math.h>
#include <stdint.h>

#define BB 4
#define NN 1024
#define CC 1024
#define HH 16
#define DH 64
#define MROWS (BB*NN)   // 4096

// ---------------- scratch (device globals; no allocation allowed) ----------
__device__ __half g_lg[BB*NN*NN];     // logits fp16, 8 MB
__device__ __half g_x16[MROWS*CC];
__device__ __half g_pre[MROWS*CC];
__device__ __half g_ctx[MROWS*CC];
__device__ __half g_q16[BB*HH*NN*DH];
__device__ __half g_k16[BB*HH*NN*DH];
__device__ __half g_v16[BB*HH*NN*DH];
__device__ __half g_wpre[CC*CC];
__device__ __half g_wq[CC*CC];
__device__ __half g_wk[CC*CC];
__device__ __half g_wv[CC*CC];
__device__ __half g_wp[CC*CC];

// ======================= portable PTX helpers ==============================
__device__ __forceinline__ uint32_t smem_to_u32(const void* p) {
    uint32_t a;
    asm("{ .reg .u64 t; cvta.to.shared.u64 t, %1; cvt.u32.u64 %0, t; }"
        : "=r"(a) : "l"(p));
    return a;
}
#define CP_ASYNC16(dst, src) \
    asm volatile("cp.async.cg.shared.global [%0], [%1], 16;" \
                 :: "r"(dst), "l"(src) : "memory")
#define CP_COMMIT() asm volatile("cp.async.commit_group;" ::: "memory")
#define CP_WAIT0()  asm volatile("cp.async.wait_group 0;" ::: "memory")

__device__ __forceinline__ void ldsm4(uint32_t* r, uint32_t addr) {
    asm volatile("ldmatrix.sync.aligned.m8n8.x4.shared.b16 {%0,%1,%2,%3}, [%4];"
        : "=r"(r[0]), "=r"(r[1]), "=r"(r[2]), "=r"(r[3]) : "r"(addr));
}
__device__ __forceinline__ void ldsm4t(uint32_t* r, uint32_t addr) {
    asm volatile("ldmatrix.sync.aligned.m8n8.x4.trans.shared.b16 {%0,%1,%2,%3}, [%4];"
        : "=r"(r[0]), "=r"(r[1]), "=r"(r[2]), "=r"(r[3]) : "r"(addr));
}
__device__ __forceinline__ void mma16816(float* c, const uint32_t* a,
                                         const uint32_t* b) {
    asm volatile("mma.sync.aligned.m16n8k16.row.col.f32.f16.f16.f32 "
        "{%0,%1,%2,%3}, {%4,%5,%6,%7}, {%8,%9}, {%0,%1,%2,%3};"
        : "+f"(c[0]), "+f"(c[1]), "+f"(c[2]), "+f"(c[3])
        : "r"(a[0]), "r"(a[1]), "r"(a[2]), "r"(a[3]), "r"(b[0]), "r"(b[1]));
}
__device__ __forceinline__ uint32_t pack_h2(float x, float y) {
    __half2 p = __floats2half2_rn(x, y);
    return *(uint32_t*)&p;
}

// ======================= prep kernels ======================================
__global__ __launch_bounds__(256) void round2h(
    const float2* __restrict__ in, __half2* __restrict__ o, int n2)
{
    int i = blockIdx.x * blockDim.x + threadIdx.x;
    if (i < n2) {
        float2 a = in[i];
        o[i] = __floats2half2_rn(a.x, a.y);
    }
}

__global__ __launch_bounds__(256) void wround_T5(
    const float* __restrict__ W0, const float* __restrict__ W1,
    const float* __restrict__ W2, const float* __restrict__ W3,
    const float* __restrict__ W4,
    __half* o0, __half* o1, __half* o2, __half* o3, __half* o4)
{
    const float* Ws[5] = {W0, W1, W2, W3, W4};
    __half* Os[5] = {o0, o1, o2, o3, o4};
    const int z = blockIdx.z;
    const float* W = Ws[z];
    __half* th = Os[z];

    __shared__ float s[32][33];
    const int tx = threadIdx.x, ty = threadIdx.y;
    const int n0 = blockIdx.x * 32, k0 = blockIdx.y * 32;
#pragma unroll
    for (int i = ty; i < 32; i += 8)
        s[i][tx] = W[(size_t)(k0 + i) * CC + n0 + tx];
    __syncthreads();
#pragma unroll
    for (int i = ty; i < 32; i += 8)
        th[(size_t)(n0 + i) * CC + k0 + tx] = __float2half(s[tx][i]);
}

// ======================= HMMA GEMM common machinery ========================
enum { EPI_LOGITS = 2, EPI_RESID = 3 };

#define OFF_A 0
#define OFF_B 8192
#define STAGE_BYTES 16384
#define SMEM_HMMA (2 * STAGE_BYTES)    // 32768 -> 2 CTAs/SM

struct GemmCore {
    uint32_t smem_u32;
    int lane, wid, wr, wc, lrow, lc, rowSel, hiH, rmod;
    __device__ __forceinline__ void init(uint32_t smem, int t) {
        smem_u32 = smem;
        lane = t & 31; wid = t >> 5;
        wr = wid & 1; wc = wid >> 1;
        lrow = t >> 2; lc = t & 3;
        rowSel = lane & 15; hiH = lane >> 4; rmod = (rowSel >> 1) & 3;
    }
    __device__ __forceinline__ void load_stage(
        const __half* Ab, const __half* Bb,
        int row0, int col0, int ch, int s) const
    {
        const size_t kb = (size_t)ch * 32 + lc * 8;
        const uint32_t sb = smem_u32 + s * STAGE_BYTES;
#pragma unroll
        for (int i = 0; i < 2; i++) {
            const int r = lrow + i * 64;
            const uint32_t so = (uint32_t)(r * 64 + ((lc ^ ((r >> 1) & 3)) * 16));
            CP_ASYNC16(sb + OFF_A + so, Ab + (size_t)(row0 + r) * CC + kb);
            CP_ASYNC16(sb + OFF_B + so, Bb + (size_t)(col0 + r) * CC + kb);
        }
    }
    __device__ __forceinline__ void run(
        const __half* Ab, const __half* Bb,
        int row0, int col0, float acc[4][4][4]) const
    {
#pragma unroll
        for (int a = 0; a < 4; a++)
#pragma unroll
            for (int b = 0; b < 4; b++)
#pragma unroll
                for (int c = 0; c < 4; c++) acc[a][b][c] = 0.0f;

        load_stage(Ab, Bb, row0, col0, 0, 0);
        CP_COMMIT();
        for (int ch = 0; ch < 32; ch++) {
            CP_WAIT0();
            __syncthreads();
            if (ch < 31) {
                load_stage(Ab, Bb, row0, col0, ch + 1, (ch + 1) & 1);
                CP_COMMIT();
            }

            const uint32_t sb = smem_u32 + (ch & 1) * STAGE_BYTES;
#pragma unroll
            for (int k16 = 0; k16 < 2; k16++) {
                const int chunk = k16 * 2 + hiH;
                uint32_t bh[4][2];
#pragma unroll
                for (int n16 = 0; n16 < 2; n16++) {
                    const int row = wc * 32 + n16 * 16 + rowSel;
                    const uint32_t off = (uint32_t)(row * 64 + ((chunk ^ rmod) * 16));
                    uint32_t rh[4];
                    ldsm4(rh, sb + OFF_B + off);
                    bh[n16 * 2][0] = rh[0]; bh[n16 * 2 + 1][0] = rh[1];
                    bh[n16 * 2][1] = rh[2]; bh[n16 * 2 + 1][1] = rh[3];
                }
#pragma unroll
                for (int mt = 0; mt < 4; mt++) {
                    const int row = wr * 64 + mt * 16 + rowSel;
                    const uint32_t off = (uint32_t)(row * 64 + ((chunk ^ rmod) * 16));
                    uint32_t ah[4];
                    ldsm4(ah, sb + OFF_A + off);
#pragma unroll
                    for (int nt = 0; nt < 4; nt++) mma16816(acc[mt][nt], ah, bh[nt]);
                }
            }
        }
    }
};

// ---- merged pre/Q/K/V GEMM ------------------------------------------------
__global__ __launch_bounds__(256, 2) void hmma_qkv(
    const __half* __restrict__ x16,
    const __half* wpre, const __half* wq, const __half* wk, const __half* wv,
    const float* __restrict__ bpre,
    __half* pre, __half* q16, __half* k16, __half* v16)
{
    extern __shared__ char smem_raw[];
    GemmCore gc_;
    gc_.init(smem_to_u32(smem_raw), threadIdx.x);

    const int g    = blockIdx.x >> 3;
    const int col0 = (blockIdx.x & 7) * 128;
    const int row0 = blockIdx.y * 128;

    const __half* Bp[4] = {wpre, wq, wk, wv};
    __half* Op[4] = {pre, q16, k16, v16};

    float acc[4][4][4];
    gc_.run(x16, Bp[g], row0, col0, acc);

    const int r0g = row0 + gc_.wr * 64 + (gc_.lane >> 2);
    const int c0g = col0 + gc_.wc * 32 + (gc_.lane & 3) * 2;
#pragma unroll
    for (int mt = 0; mt < 4; mt++) {
#pragma unroll
        for (int nt = 0; nt < 4; nt++) {
            const int gcc = c0g + nt * 8;
#pragma unroll
            for (int half = 0; half < 2; half++) {
                const int gr = r0g + mt * 16 + half * 8;
                float v0 = acc[mt][nt][half * 2 + 0];
                float v1 = acc[mt][nt][half * 2 + 1];
                if (g == 0) {
                    v0 += bpre[gcc]; v1 += bpre[gcc + 1];
                    v0 = v0 / (1.0f + __expf(-v0));
                    v1 = v1 / (1.0f + __expf(-v1));
                    *(__half2*)(Op[0] + (size_t)gr * CC + gcc) =
                        __floats2half2_rn(v0, v1);
                } else {
                    const int b = gr >> 10, n = gr & (NN - 1);
                    const int h = gcc >> 6, dh = gcc & 63;
                    const size_t o = ((size_t)(b * HH + h) * NN + n) * DH + dh;
                    *(__half2*)(Op[g] + o) = __floats2half2_rn(v0, v1);
                }
            }
        }
    }
}

// ---- logits (symmetric upper-tri, fp16 out) + proj/resid GEMM -------------
__global__ __launch_bounds__(256, 2) void hmma_gemm(
    const __half* __restrict__ As, const __half* __restrict__ Bs,
    const float* __restrict__ bias, const float* __restrict__ resid,
    float* __restrict__ outF, __half* __restrict__ outH,
    int mode, long long bsA, long long bsB)
{
    extern __shared__ char smem_raw[];
    GemmCore gc_;
    gc_.init(smem_to_u32(smem_raw), threadIdx.x);

    int row0, col0, ti = 0, tj = 0;
    if (mode == EPI_LOGITS) {
        int li = blockIdx.x, rem = 8;
        while (li >= rem) { li -= rem; rem--; ti++; }
        tj = ti + li;
        row0 = ti * 128; col0 = tj * 128;
    } else {
        row0 = blockIdx.y * 128;
        col0 = blockIdx.x * 128;
    }
    const int z = blockIdx.z;
    const __half* Ab = As + (size_t)z * bsA;
    const __half* Bb = Bs + (size_t)z * bsB;
    __half* oH = outH ? outH + (size_t)z * NN * NN : nullptr;

    float acc[4][4][4];
    gc_.run(Ab, Bb, row0, col0, acc);

    const int r0g = row0 + gc_.wr * 64 + (gc_.lane >> 2);
    const int c0g = col0 + gc_.wc * 32 + (gc_.lane & 3) * 2;
#pragma unroll
    for (int mt = 0; mt < 4; mt++) {
#pragma unroll
        for (int nt = 0; nt < 4; nt++) {
            const int gcc = c0g + nt * 8;
#pragma unroll
            for (int half = 0; half < 2; half++) {
                const int gr = r0g + mt * 16 + half * 8;
                float v0 = acc[mt][nt][half * 2 + 0];
                float v1 = acc[mt][nt][half * 2 + 1];
                if (mode == EPI_LOGITS) {
                    v0 *= 0.03125f; v1 *= 0.03125f;
                    __half h0 = __float2half(v0), h1 = __float2half(v1);
                    *(__half2*)(oH + (size_t)gr * NN + gcc) = __halves2half2(h0, h1);
                    if (ti != tj) {
                        oH[(size_t)gcc * NN + gr]       = h0;
                        oH[(size_t)(gcc + 1) * NN + gr] = h1;
                    }
                } else { // EPI_RESID
                    const size_t ro = (size_t)gr * CC + gcc;
                    outF[ro]     = v0 + bias[gcc]     + resid[ro];
                    outF[ro + 1] = v1 + bias[gcc + 1] + resid[ro + 1];
                }
            }
        }
    }
}

// ======================= HMMA flash attention (128-q tile) =================
#define SMQ 0
#define KVBASE 16384
#define KVST 16384
#define KV_K 0
#define KV_V 8192
#define SMEM_FATT (KVBASE + 2 * KVST)    // 49152

__global__ __launch_bounds__(256, 2) void fattn(
    const __half* __restrict__ q16, const __half* __restrict__ k16,
    const __half* __restrict__ v16,
    const __half* __restrict__ lg,
    const float* __restrict__ pi_p, __half* __restrict__ ctx)
{
    extern __shared__ char sm[];
    const uint32_t sb = smem_to_u32(sm);
    const int t = threadIdx.x, lane = t & 31, w = t >> 5;
    const int bh = blockIdx.y, b = bh >> 4, h = bh & 15;
    const int q0 = blockIdx.x * 128;
    const size_t hoff = (size_t)bh * NN * DH;
    const float pi = pi_p[0];

#pragma unroll
    for (int i = 0; i < 4; i++) {
        const int id = t + i * 256;
        const int r = id >> 3, c = id & 7;
        const uint32_t off = (uint32_t)(r * 128 + ((c ^ (r & 7)) * 16));
        CP_ASYNC16(sb + SMQ + off, q16 + hoff + (size_t)(q0 + r) * DH + c * 8);
    }
    CP_COMMIT();

    auto load_kv = [&](int kt, int buf) {
        const uint32_t kvb = sb + KVBASE + buf * KVST;
#pragma unroll
        for (int i = 0; i < 2; i++) {
            const int id = t + i * 256;
            const int r = id >> 3, c = id & 7;
            const uint32_t off = (uint32_t)(r * 128 + ((c ^ (r & 7)) * 16));
            const size_t g = hoff + (size_t)(kt * 64 + r) * DH + c * 8;
            CP_ASYNC16(kvb + KV_K + off, k16 + g);
            CP_ASYNC16(kvb + KV_V + off, v16 + g);
        }
    };

    load_kv(0, 0);
    CP_COMMIT();

    float S[8][4], O[8][4];
#pragma unroll
    for (int j = 0; j < 8; j++)
#pragma unroll
        for (int c = 0; c < 4; c++) O[j][c] = 0.0f;
    float m0 = -1e30f, m1 = -1e30f, l0 = 0.0f, l1 = 0.0f;

    const int qr = w * 16 + (lane >> 2);
    const __half* lgr = lg + (size_t)b * NN * NN + (size_t)(q0 + qr) * NN;
    const int rowSel = lane & 15, hiH = lane >> 4;

    for (int kt = 0; kt < 16; kt++) {
        const int mk = kt * 64;
        CP_WAIT0();
        __syncthreads();
        if (kt < 15) { load_kv(kt + 1, (kt + 1) & 1); CP_COMMIT(); }

        const uint32_t kvb = sb + KVBASE + (kt & 1) * KVST;

        // ---- S = Q K^T ----
#pragma unroll
        for (int j = 0; j < 8; j++)
#pragma unroll
            for (int c = 0; c < 4; c++) S[j][c] = 0.0f;

#pragma unroll
        for (int kc = 0; kc < 4; kc++) {
            const int chunk = 2 * kc + hiH;
            uint32_t aq[4];
            {
                const int row = w * 16 + rowSel;
                const uint32_t off = (uint32_t)(row * 128 + ((chunk ^ (row & 7)) * 16));
                ldsm4(aq, sb + SMQ + off);
            }
#pragma unroll
            for (int j16 = 0; j16 < 4; j16++) {
                const int row = j16 * 16 + rowSel;
                const uint32_t off = (uint32_t)(row * 128 + ((chunk ^ (row & 7)) * 16));
                uint32_t rh[4];
                ldsm4(rh, kvb + KV_K + off);
                uint32_t b0[2] = {rh[0], rh[2]}, b1[2] = {rh[1], rh[3]};
                mma16816(S[2 * j16],     aq, b0);
                mma16816(S[2 * j16 + 1], aq, b1);
            }
        }

        // ---- bias (fp16 logits) + online softmax ----
        float mx0 = -1e30f, mx1 = -1e30f;
#pragma unroll
        for (int j = 0; j < 8; j++) {
            const int cix = mk + j * 8 + (lane & 3) * 2;
            float2 L0 = __half22float2(*(const __half2*)(lgr + cix));
            float2 L1 = __half22float2(*(const __half2*)(lgr + 8 * NN + cix));
            S[j][0] = S[j][0] * 0.125f + pi * L0.x;
            S[j][1] = S[j][1] * 0.125f + pi * L0.y;
            S[j][2] = S[j][2] * 0.125f + pi * L1.x;
            S[j][3] = S[j][3] * 0.125f + pi * L1.y;
            mx0 = fmaxf(mx0, fmaxf(S[j][0], S[j][1]));
            mx1 = fmaxf(mx1, fmaxf(S[j][2], S[j][3]));
        }
        mx0 = fmaxf(mx0, __shfl_xor_sync(0xffffffffu, mx0, 1));
        mx0 = fmaxf(mx0, __shfl_xor_sync(0xffffffffu, mx0, 2));
        mx1 = fmaxf(mx1, __shfl_xor_sync(0xffffffffu, mx1, 1));
        mx1 = fmaxf(mx1, __shfl_xor_sync(0xffffffffu, mx1, 2));
        const float mn0 = fmaxf(m0, mx0), mn1 = fmaxf(m1, mx1);
        const float a0s = __expf(m0 - mn0), a1s = __expf(m1 - mn1);
        m0 = mn0; m1 = mn1;
        float s0 = 0.0f, s1 = 0.0f;
#pragma unroll
        for (int j = 0; j < 8; j++) {
            S[j][0] = __expf(S[j][0] - mn0); S[j][1] = __expf(S[j][1] - mn0);
            S[j][2] = __expf(S[j][2] - mn1); S[j][3] = __expf(S[j][3] - mn1);
            s0 += S[j][0] + S[j][1];
            s1 += S[j][2] + S[j][3];
        }
        s0 += __shfl_xor_sync(0xffffffffu, s0, 1);
        s0 += __shfl_xor_sync(0xffffffffu, s0, 2);
        s1 += __shfl_xor_sync(0xffffffffu, s1, 1);
        s1 += __shfl_xor_sync(0xffffffffu, s1, 2);
        l0 = l0 * a0s + s0; l1 = l1 * a1s + s1;
#pragma unroll
        for (int j = 0; j < 8; j++) {
            O[j][0] *= a0s; O[j][1] *= a0s; O[j][2] *= a1s; O[j][3] *= a1s;
        }

        // ---- O += P V ----
#pragma unroll
        for (int kc = 0; kc < 4; kc++) {
            uint32_t ph[4];
#pragma unroll
            for (int half = 0; half < 2; half++) {
                const int j = 2 * kc + half;
                ph[half * 2 + 0] = pack_h2(S[j][0], S[j][1]);
                ph[half * 2 + 1] = pack_h2(S[j][2], S[j][3]);
            }
#pragma unroll
            for (int jc = 0; jc < 4; jc++) {
                const int row = kc * 16 + rowSel;
                const int chunk = 2 * jc + hiH;
                const uint32_t off = (uint32_t)(row * 128 + ((chunk ^ (row & 7)) * 16));
                uint32_t rv[4];
                ldsm4t(rv, kvb + KV_V + off);
                uint32_t v0[2] = {rv[0], rv[1]}, v1[2] = {rv[2], rv[3]};
                mma16816(O[2 * jc],     ph, v0);
                mma16816(O[2 * jc + 1], ph, v1);
            }
        }
    }

    // ---- epilogue ----
    const float inv0 = 1.0f / l0, inv1 = 1.0f / l1;
    const size_t r0o = (size_t)(b * NN + q0 + qr) * CC;
    const size_t r1o = r0o + (size_t)8 * CC;
    const int cb = h * DH + (lane & 3) * 2;
#pragma unroll
    for (int dj = 0; dj < 8; dj++) {
        const int col = cb + dj * 8;
        *(__half2*)(ctx + r0o + col) = __floats2half2_rn(O[dj][0] * inv0, O[dj][1] * inv0);
        *(__half2*)(ctx + r1o + col) = __floats2half2_rn(O[dj][2] * inv1, O[dj][3] * inv1);
    }
}

// ---------------------------------------------------------------------------
extern "C" void kernel_launch(void* const* d_in, const int* in_sizes, int n_in,
                              void* d_out, int out_size)
{
    (void)in_sizes; (void)n_in; (void)out_size;
    const float* x     = (const float*)d_in[0];
    const float* Wq    = (const float*)d_in[1];
    const float* Wk    = (const float*)d_in[2];
    const float* Wv    = (const float*)d_in[3];
    const float* Wproj = (const float*)d_in[4];
    const float* bproj = (const float*)d_in[5];
    const float* Wpre  = (const float*)d_in[6];
    const float* bpre  = (const float*)d_in[7];
    const float* pi    = (const float*)d_in[8];
    float* out = (float*)d_out;

    __half *lg;
    __half *x16, *pre, *ctx, *q16, *k16, *v16;
    __half *wpre, *wq, *wk, *wv, *wp;
    cudaGetSymbolAddress((void**)&lg,   g_lg);
    cudaGetSymbolAddress((void**)&x16,  g_x16);
    cudaGetSymbolAddress((void**)&pre,  g_pre);
    cudaGetSymbolAddress((void**)&ctx,  g_ctx);
    cudaGetSymbolAddress((void**)&q16,  g_q16);
    cudaGetSymbolAddress((void**)&k16,  g_k16);
    cudaGetSymbolAddress((void**)&v16,  g_v16);
    cudaGetSymbolAddress((void**)&wpre, g_wpre);
    cudaGetSymbolAddress((void**)&wq,   g_wq);
    cudaGetSymbolAddress((void**)&wk,   g_wk);
    cudaGetSymbolAddress((void**)&wv,   g_wv);
    cudaGetSymbolAddress((void**)&wp,   g_wp);

    cudaFuncSetAttribute(hmma_qkv,  cudaFuncAttributeMaxDynamicSharedMemorySize, SMEM_HMMA);
    cudaFuncSetAttribute(hmma_gemm, cudaFuncAttributeMaxDynamicSharedMemorySize, SMEM_HMMA);
    cudaFuncSetAttribute(fattn,     cudaFuncAttributeMaxDynamicSharedMemorySize, SMEM_FATT);

    // ---- prep ----
    dim3 wst(32, 8), wsg(32, 32, 5);
    wround_T5<<<wsg, wst>>>(Wpre, Wq, Wk, Wv, Wproj, wpre, wq, wk, wv, wp);
    const int n2 = MROWS * CC / 2;
    round2h<<<(n2 + 255) / 256, 256>>>((const float2*)x, (__half2*)x16, n2);

    // ---- merged pre/Q/K/V GEMM ----
    dim3 mb(256);
    dim3 gqkv(32, MROWS / 128, 1);
    hmma_qkv<<<gqkv, mb, SMEM_HMMA>>>(x16, wpre, wq, wk, wv, bpre,
                                      pre, q16, k16, v16);

    // ---- logits GEMM (symmetric: 36 upper-tri tiles/batch, fp16 out) ----
    dim3 glog(36, 1, BB);
    hmma_gemm<<<glog, mb, SMEM_HMMA>>>(pre, pre, nullptr, nullptr,
                                       nullptr, lg, EPI_LOGITS,
                                       (long long)NN * CC, (long long)NN * CC);

    // ---- HMMA flash attention ----
    dim3 ga(NN / 128, BB * HH);
    fattn<<<ga, 256, SMEM_FATT>>>(q16, k16, v16, lg, pi, ctx);

    // ---- projection + residual ----
    dim3 gl(CC / 128, MROWS / 128, 1);
    hmma_gemm<<<gl, mb, SMEM_HMMA>>>(ctx, wp, bproj, x,
                                     out, nullptr, EPI_RESID, 0, 0);
}

// round 15
// speedup vs baseline: 1.1137x; 1.0146x over previous
#include <cuda_runtime.h>
#include <cuda_fp16.h>
#include <math.h>
#include <stdint.h>

#define BB 4
#define NN 1024
#define CC 1024
#define HH 16
#define DH 64
#define MROWS (BB*NN)   // 4096

// ---------------- scratch (device globals; no allocation allowed) ----------
__device__ __half g_lg[BB*NN*NN];     // logits fp16, 8 MB
__device__ __half g_x16[MROWS*CC];
__device__ __half g_pre[MROWS*CC];
__device__ __half g_ctx[MROWS*CC];
__device__ __half g_q16[BB*HH*NN*DH];
__device__ __half g_k16[BB*HH*NN*DH];
__device__ __half g_v16[BB*HH*NN*DH];
__device__ __half g_wpre[CC*CC];
__device__ __half g_wq[CC*CC];
__device__ __half g_wk[CC*CC];
__device__ __half g_wv[CC*CC];
__device__ __half g_wp[CC*CC];

// ======================= portable PTX helpers ==============================
__device__ __forceinline__ uint32_t smem_to_u32(const void* p) {
    uint32_t a;
    asm("{ .reg .u64 t; cvta.to.shared.u64 t, %1; cvt.u32.u64 %0, t; }"
        : "=r"(a) : "l"(p));
    return a;
}
#define CP_ASYNC16(dst, src) \
    asm volatile("cp.async.cg.shared.global [%0], [%1], 16;" \
                 :: "r"(dst), "l"(src) : "memory")
#define CP_COMMIT() asm volatile("cp.async.commit_group;" ::: "memory")
#define CP_WAIT0()  asm volatile("cp.async.wait_group 0;" ::: "memory")

__device__ __forceinline__ void ldsm4(uint32_t* r, uint32_t addr) {
    asm volatile("ldmatrix.sync.aligned.m8n8.x4.shared.b16 {%0,%1,%2,%3}, [%4];"
        : "=r"(r[0]), "=r"(r[1]), "=r"(r[2]), "=r"(r[3]) : "r"(addr));
}
__device__ __forceinline__ void ldsm4t(uint32_t* r, uint32_t addr) {
    asm volatile("ldmatrix.sync.aligned.m8n8.x4.trans.shared.b16 {%0,%1,%2,%3}, [%4];"
        : "=r"(r[0]), "=r"(r[1]), "=r"(r[2]), "=r"(r[3]) : "r"(addr));
}
__device__ __forceinline__ void mma16816(float* c, const uint32_t* a,
                                         const uint32_t* b) {
    asm volatile("mma.sync.aligned.m16n8k16.row.col.f32.f16.f16.f32 "
        "{%0,%1,%2,%3}, {%4,%5,%6,%7}, {%8,%9}, {%0,%1,%2,%3};"
        : "+f"(c[0]), "+f"(c[1]), "+f"(c[2]), "+f"(c[3])
        : "r"(a[0]), "r"(a[1]), "r"(a[2]), "r"(a[3]), "r"(b[0]), "r"(b[1]));
}
__device__ __forceinline__ uint32_t pack_h2(float x, float y) {
    __half2 p = __floats2half2_rn(x, y);
    return *(uint32_t*)&p;
}

// ======================= prep kernels ======================================
__global__ __launch_bounds__(256) void round2h(
    const float2* __restrict__ in, __half2* __restrict__ o, int n2)
{
    int i = blockIdx.x * blockDim.x + threadIdx.x;
    if (i < n2) {
        float2 a = in[i];
        o[i] = __floats2half2_rn(a.x, a.y);
    }
}

__global__ __launch_bounds__(256) void wround_T5(
    const float* __restrict__ W0, const float* __restrict__ W1,
    const float* __restrict__ W2, const float* __restrict__ W3,
    const float* __restrict__ W4,
    __half* o0, __half* o1, __half* o2, __half* o3, __half* o4)
{
    const float* Ws[5] = {W0, W1, W2, W3, W4};
    __half* Os[5] = {o0, o1, o2, o3, o4};
    const int z = blockIdx.z;
    const float* W = Ws[z];
    __half* th = Os[z];

    __shared__ float s[32][33];
    const int tx = threadIdx.x, ty = threadIdx.y;
    const int n0 = blockIdx.x * 32, k0 = blockIdx.y * 32;
#pragma unroll
    for (int i = ty; i < 32; i += 8)
        s[i][tx] = W[(size_t)(k0 + i) * CC + n0 + tx];
    __syncthreads();
#pragma unroll
    for (int i = ty; i < 32; i += 8)
        th[(size_t)(n0 + i) * CC + k0 + tx] = __float2half(s[tx][i]);
}

// ======================= HMMA GEMM common machinery ========================
enum { EPI_LOGITS = 2, EPI_RESID = 3 };

#define OFF_A 0
#define OFF_B 8192
#define STAGE_BYTES 16384
#define SMEM_HMMA (2 * STAGE_BYTES)    // 32768 -> 2 CTAs/SM

struct GemmCore {
    uint32_t smem_u32;
    int lane, wid, wr, wc, lrow, lc, rowSel, hiH, rmod;
    __device__ __forceinline__ void init(uint32_t smem, int t) {
        smem_u32 = smem;
        lane = t & 31; wid = t >> 5;
        wr = wid & 1; wc = wid >> 1;
        lrow = t >> 2; lc = t & 3;
        rowSel = lane & 15; hiH = lane >> 4; rmod = (rowSel >> 1) & 3;
    }
    __device__ __forceinline__ void load_stage(
        const __half* Ab, const __half* Bb,
        int row0, int col0, int ch, int s) const
    {
        const size_t kb = (size_t)ch * 32 + lc * 8;
        const uint32_t sb = smem_u32 + s * STAGE_BYTES;
#pragma unroll
        for (int i = 0; i < 2; i++) {
            const int r = lrow + i * 64;
            const uint32_t so = (uint32_t)(r * 64 + ((lc ^ ((r >> 1) & 3)) * 16));
            CP_ASYNC16(sb + OFF_A + so, Ab + (size_t)(row0 + r) * CC + kb);
            CP_ASYNC16(sb + OFF_B + so, Bb + (size_t)(col0 + r) * CC + kb);
        }
    }
    __device__ __forceinline__ void run(
        const __half* Ab, const __half* Bb,
        int row0, int col0, float acc[4][4][4]) const
    {
#pragma unroll
        for (int a = 0; a < 4; a++)
#pragma unroll
            for (int b = 0; b < 4; b++)
#pragma unroll
                for (int c = 0; c < 4; c++) acc[a][b][c] = 0.0f;

        load_stage(Ab, Bb, row0, col0, 0, 0);
        CP_COMMIT();
        for (int ch = 0; ch < 32; ch++) {
            CP_WAIT0();
            __syncthreads();
            if (ch < 31) {
                load_stage(Ab, Bb, row0, col0, ch + 1, (ch + 1) & 1);
                CP_COMMIT();
            }

            const uint32_t sb = smem_u32 + (ch & 1) * STAGE_BYTES;
#pragma unroll
            for (int k16 = 0; k16 < 2; k16++) {
                const int chunk = k16 * 2 + hiH;
                uint32_t bh[4][2];
#pragma unroll
                for (int n16 = 0; n16 < 2; n16++) {
                    const int row = wc * 32 + n16 * 16 + rowSel;
                    const uint32_t off = (uint32_t)(row * 64 + ((chunk ^ rmod) * 16));
                    uint32_t rh[4];
                    ldsm4(rh, sb + OFF_B + off);
                    bh[n16 * 2][0] = rh[0]; bh[n16 * 2 + 1][0] = rh[1];
                    bh[n16 * 2][1] = rh[2]; bh[n16 * 2 + 1][1] = rh[3];
                }
#pragma unroll
                for (int mt = 0; mt < 4; mt++) {
                    const int row = wr * 64 + mt * 16 + rowSel;
                    const uint32_t off = (uint32_t)(row * 64 + ((chunk ^ rmod) * 16));
                    uint32_t ah[4];
                    ldsm4(ah, sb + OFF_A + off);
#pragma unroll
                    for (int nt = 0; nt < 4; nt++) mma16816(acc[mt][nt], ah, bh[nt]);
                }
            }
        }
    }
};

// ---- pre/Q/K/V GEMM; gbase selects first group (0 = pre only pass) --------
__global__ __launch_bounds__(256, 2) void hmma_qkv(
    const __half* __restrict__ x16,
    const __half* wpre, const __half* wq, const __half* wk, const __half* wv,
    const float* __restrict__ bpre,
    __half* pre, __half* q16, __half* k16, __half* v16, int gbase)
{
    extern __shared__ char smem_raw[];
    GemmCore gc_;
    gc_.init(smem_to_u32(smem_raw), threadIdx.x);

    const int g    = gbase + (blockIdx.x >> 3);
    const int col0 = (blockIdx.x & 7) * 128;
    const int row0 = blockIdx.y * 128;

    const __half* Bp[4] = {wpre, wq, wk, wv};
    __half* Op[4] = {pre, q16, k16, v16};

    float acc[4][4][4];
    gc_.run(x16, Bp[g], row0, col0, acc);

    const int r0g = row0 + gc_.wr * 64 + (gc_.lane >> 2);
    const int c0g = col0 + gc_.wc * 32 + (gc_.lane & 3) * 2;
#pragma unroll
    for (int mt = 0; mt < 4; mt++) {
#pragma unroll
        for (int nt = 0; nt < 4; nt++) {
            const int gcc = c0g + nt * 8;
#pragma unroll
            for (int half = 0; half < 2; half++) {
                const int gr = r0g + mt * 16 + half * 8;
                float v0 = acc[mt][nt][half * 2 + 0];
                float v1 = acc[mt][nt][half * 2 + 1];
                if (g == 0) {
                    v0 += bpre[gcc]; v1 += bpre[gcc + 1];
                    v0 = v0 / (1.0f + __expf(-v0));
                    v1 = v1 / (1.0f + __expf(-v1));
                    *(__half2*)(Op[0] + (size_t)gr * CC + gcc) =
                        __floats2half2_rn(v0, v1);
                } else {
                    const int b = gr >> 10, n = gr & (NN - 1);
                    const int h = gcc >> 6, dh = gcc & 63;
                    const size_t o = ((size_t)(b * HH + h) * NN + n) * DH + dh;
                    *(__half2*)(Op[g] + o) = __floats2half2_rn(v0, v1);
                }
            }
        }
    }
}

// ---- logits (symmetric upper-tri, fp16 out) + proj/resid GEMM -------------
__global__ __launch_bounds__(256, 2) void hmma_gemm(
    const __half* __restrict__ As, const __half* __restrict__ Bs,
    const float* __restrict__ bias, const float* __restrict__ resid,
    float* __restrict__ outF, __half* __restrict__ outH,
    int mode, long long bsA, long long bsB)
{
    extern __shared__ char smem_raw[];
    GemmCore gc_;
    gc_.init(smem_to_u32(smem_raw), threadIdx.x);

    int row0, col0, ti = 0, tj = 0;
    if (mode == EPI_LOGITS) {
        int li = blockIdx.x, rem = 8;
        while (li >= rem) { li -= rem; rem--; ti++; }
        tj = ti + li;
        row0 = ti * 128; col0 = tj * 128;
    } else {
        row0 = blockIdx.y * 128;
        col0 = blockIdx.x * 128;
    }
    const int z = blockIdx.z;
    const __half* Ab = As + (size_t)z * bsA;
    const __half* Bb = Bs + (size_t)z * bsB;
    __half* oH = outH ? outH + (size_t)z * NN * NN : nullptr;

    float acc[4][4][4];
    gc_.run(Ab, Bb, row0, col0, acc);

    const int r0g = row0 + gc_.wr * 64 + (gc_.lane >> 2);
    const int c0g = col0 + gc_.wc * 32 + (gc_.lane & 3) * 2;
#pragma unroll
    for (int mt = 0; mt < 4; mt++) {
#pragma unroll
        for (int nt = 0; nt < 4; nt++) {
            const int gcc = c0g + nt * 8;
#pragma unroll
            for (int half = 0; half < 2; half++) {
                const int gr = r0g + mt * 16 + half * 8;
                float v0 = acc[mt][nt][half * 2 + 0];
                float v1 = acc[mt][nt][half * 2 + 1];
                if (mode == EPI_LOGITS) {
                    v0 *= 0.03125f; v1 *= 0.03125f;
                    __half h0 = __float2half(v0), h1 = __float2half(v1);
                    *(__half2*)(oH + (size_t)gr * NN + gcc) = __halves2half2(h0, h1);
                    if (ti != tj) {
                        oH[(size_t)gcc * NN + gr]       = h0;
                        oH[(size_t)(gcc + 1) * NN + gr] = h1;
                    }
                } else { // EPI_RESID
                    const size_t ro = (size_t)gr * CC + gcc;
                    outF[ro]     = v0 + bias[gcc]     + resid[ro];
                    outF[ro + 1] = v1 + bias[gcc + 1] + resid[ro + 1];
                }
            }
        }
    }
}

// ======================= HMMA flash attention (128-q tile) =================
#define SMQ 0
#define KVBASE 16384
#define KVST 16384
#define KV_K 0
#define KV_V 8192
#define SMEM_FATT (KVBASE + 2 * KVST)    // 49152

__global__ __launch_bounds__(256, 2) void fattn(
    const __half* __restrict__ q16, const __half* __restrict__ k16,
    const __half* __restrict__ v16,
    const __half* __restrict__ lg,
    const float* __restrict__ pi_p, __half* __restrict__ ctx)
{
    extern __shared__ char sm[];
    const uint32_t sb = smem_to_u32(sm);
    const int t = threadIdx.x, lane = t & 31, w = t >> 5;
    const int bh = blockIdx.y, b = bh >> 4, h = bh & 15;
    const int q0 = blockIdx.x * 128;
    const size_t hoff = (size_t)bh * NN * DH;
    const float pi = pi_p[0];

#pragma unroll
    for (int i = 0; i < 4; i++) {
        const int id = t + i * 256;
        const int r = id >> 3, c = id & 7;
        const uint32_t off = (uint32_t)(r * 128 + ((c ^ (r & 7)) * 16));
        CP_ASYNC16(sb + SMQ + off, q16 + hoff + (size_t)(q0 + r) * DH + c * 8);
    }
    CP_COMMIT();

    auto load_kv = [&](int kt, int buf) {
        const uint32_t kvb = sb + KVBASE + buf * KVST;
#pragma unroll
        for (int i = 0; i < 2; i++) {
            const int id = t + i * 256;
            const int r = id >> 3, c = id & 7;
            const uint32_t off = (uint32_t)(r * 128 + ((c ^ (r & 7)) * 16));
            const size_t g = hoff + (size_t)(kt * 64 + r) * DH + c * 8;
            CP_ASYNC16(kvb + KV_K + off, k16 + g);
            CP_ASYNC16(kvb + KV_V + off, v16 + g);
        }
    };

    load_kv(0, 0);
    CP_COMMIT();

    float S[8][4], O[8][4];
#pragma unroll
    for (int j = 0; j < 8; j++)
#pragma unroll
        for (int c = 0; c < 4; c++) O[j][c] = 0.0f;
    float m0 = -1e30f, m1 = -1e30f, l0 = 0.0f, l1 = 0.0f;

    const int qr = w * 16 + (lane >> 2);
    const __half* lgr = lg + (size_t)b * NN * NN + (size_t)(q0 + qr) * NN;
    const int rowSel = lane & 15, hiH = lane >> 4;

    for (int kt = 0; kt < 16; kt++) {
        const int mk = kt * 64;
        CP_WAIT0();
        __syncthreads();
        if (kt < 15) { load_kv(kt + 1, (kt + 1) & 1); CP_COMMIT(); }

        const uint32_t kvb = sb + KVBASE + (kt & 1) * KVST;

        // ---- S = Q K^T ----
#pragma unroll
        for (int j = 0; j < 8; j++)
#pragma unroll
            for (int c = 0; c < 4; c++) S[j][c] = 0.0f;

#pragma unroll
        for (int kc = 0; kc < 4; kc++) {
            const int chunk = 2 * kc + hiH;
            uint32_t aq[4];
            {
                const int row = w * 16 + rowSel;
                const uint32_t off = (uint32_t)(row * 128 + ((chunk ^ (row & 7)) * 16));
                ldsm4(aq, sb + SMQ + off);
            }
#pragma unroll
            for (int j16 = 0; j16 < 4; j16++) {
                const int row = j16 * 16 + rowSel;
                const uint32_t off = (uint32_t)(row * 128 + ((chunk ^ (row & 7)) * 16));
                uint32_t rh[4];
                ldsm4(rh, kvb + KV_K + off);
                uint32_t b0[2] = {rh[0], rh[2]}, b1[2] = {rh[1], rh[3]};
                mma16816(S[2 * j16],     aq, b0);
                mma16816(S[2 * j16 + 1], aq, b1);
            }
        }

        // ---- bias (fp16 logits) + online softmax ----
        float mx0 = -1e30f, mx1 = -1e30f;
#pragma unroll
        for (int j = 0; j < 8; j++) {
            const int cix = mk + j * 8 + (lane & 3) * 2;
            float2 L0 = __half22float2(*(const __half2*)(lgr + cix));
            float2 L1 = __half22float2(*(const __half2*)(lgr + 8 * NN + cix));
            S[j][0] = S[j][0] * 0.125f + pi * L0.x;
            S[j][1] = S[j][1] * 0.125f + pi * L0.y;
            S[j][2] = S[j][2] * 0.125f + pi * L1.x;
            S[j][3] = S[j][3] * 0.125f + pi * L1.y;
            mx0 = fmaxf(mx0, fmaxf(S[j][0], S[j][1]));
            mx1 = fmaxf(mx1, fmaxf(S[j][2], S[j][3]));
        }
        mx0 = fmaxf(mx0, __shfl_xor_sync(0xffffffffu, mx0, 1));
        mx0 = fmaxf(mx0, __shfl_xor_sync(0xffffffffu, mx0, 2));
        mx1 = fmaxf(mx1, __shfl_xor_sync(0xffffffffu, mx1, 1));
        mx1 = fmaxf(mx1, __shfl_xor_sync(0xffffffffu, mx1, 2));
        const float mn0 = fmaxf(m0, mx0), mn1 = fmaxf(m1, mx1);
        const float a0s = __expf(m0 - mn0), a1s = __expf(m1 - mn1);
        m0 = mn0; m1 = mn1;
        float s0 = 0.0f, s1 = 0.0f;
#pragma unroll
        for (int j = 0; j < 8; j++) {
            S[j][0] = __expf(S[j][0] - mn0); S[j][1] = __expf(S[j][1] - mn0);
            S[j][2] = __expf(S[j][2] - mn1); S[j][3] = __expf(S[j][3] - mn1);
            s0 += S[j][0] + S[j][1];
            s1 += S[j][2] + S[j][3];
        }
        s0 += __shfl_xor_sync(0xffffffffu, s0, 1);
        s0 += __shfl_xor_sync(0xffffffffu, s0, 2);
        s1 += __shfl_xor_sync(0xffffffffu, s1, 1);
        s1 += __shfl_xor_sync(0xffffffffu, s1, 2);
        l0 = l0 * a0s + s0; l1 = l1 * a1s + s1;
#pragma unroll
        for (int j = 0; j < 8; j++) {
            O[j][0] *= a0s; O[j][1] *= a0s; O[j][2] *= a1s; O[j][3] *= a1s;
        }

        // ---- O += P V ----
#pragma unroll
        for (int kc = 0; kc < 4; kc++) {
            uint32_t ph[4];
#pragma unroll
            for (int half = 0; half < 2; half++) {
                const int j = 2 * kc + half;
                ph[half * 2 + 0] = pack_h2(S[j][0], S[j][1]);
                ph[half * 2 + 1] = pack_h2(S[j][2], S[j][3]);
            }
#pragma unroll
            for (int jc = 0; jc < 4; jc++) {
                const int row = kc * 16 + rowSel;
                const int chunk = 2 * jc + hiH;
                const uint32_t off = (uint32_t)(row * 128 + ((chunk ^ (row & 7)) * 16));
                uint32_t rv[4];
                ldsm4t(rv, kvb + KV_V + off);
                uint32_t v0[2] = {rv[0], rv[1]}, v1[2] = {rv[2], rv[3]};
                mma16816(O[2 * jc],     ph, v0);
                mma16816(O[2 * jc + 1], ph, v1);
            }
        }
    }

    // ---- epilogue ----
    const float inv0 = 1.0f / l0, inv1 = 1.0f / l1;
    const size_t r0o = (size_t)(b * NN + q0 + qr) * CC;
    const size_t r1o = r0o + (size_t)8 * CC;
    const int cb = h * DH + (lane & 3) * 2;
#pragma unroll
    for (int dj = 0; dj < 8; dj++) {
        const int col = cb + dj * 8;
        *(__half2*)(ctx + r0o + col) = __floats2half2_rn(O[dj][0] * inv0, O[dj][1] * inv0);
        *(__half2*)(ctx + r1o + col) = __floats2half2_rn(O[dj][2] * inv1, O[dj][3] * inv1);
    }
}

// ---------------------------------------------------------------------------
static cudaStream_t get_side_stream() {
    static cudaStream_t s = []() {
        cudaStream_t st;
        cudaStreamCreateWithFlags(&st, cudaStreamNonBlocking);
        return st;
    }();
    return s;
}
static cudaEvent_t get_event(int i) {
    static cudaEvent_t e[2] = { []() { cudaEvent_t x;
        cudaEventCreateWithFlags(&x, cudaEventDisableTiming); return x; }(),
        []() { cudaEvent_t x;
        cudaEventCreateWithFlags(&x, cudaEventDisableTiming); return x; }() };
    return e[i];
}

extern "C" void kernel_launch(void* const* d_in, const int* in_sizes, int n_in,
                              void* d_out, int out_size)
{
    (void)in_sizes; (void)n_in; (void)out_size;
    const float* x     = (const float*)d_in[0];
    const float* Wq    = (const float*)d_in[1];
    const float* Wk    = (const float*)d_in[2];
    const float* Wv    = (const float*)d_in[3];
    const float* Wproj = (const float*)d_in[4];
    const float* bproj = (const float*)d_in[5];
    const float* Wpre  = (const float*)d_in[6];
    const float* bpre  = (const float*)d_in[7];
    const float* pi    = (const float*)d_in[8];
    float* out = (float*)d_out;

    __half *lg;
    __half *x16, *pre, *ctx, *q16, *k16, *v16;
    __half *wpre, *wq, *wk, *wv, *wp;
    cudaGetSymbolAddress((void**)&lg,   g_lg);
    cudaGetSymbolAddress((void**)&x16,  g_x16);
    cudaGetSymbolAddress((void**)&pre,  g_pre);
    cudaGetSymbolAddress((void**)&ctx,  g_ctx);
    cudaGetSymbolAddress((void**)&q16,  g_q16);
    cudaGetSymbolAddress((void**)&k16,  g_k16);
    cudaGetSymbolAddress((void**)&v16,  g_v16);
    cudaGetSymbolAddress((void**)&wpre, g_wpre);
    cudaGetSymbolAddress((void**)&wq,   g_wq);
    cudaGetSymbolAddress((void**)&wk,   g_wk);
    cudaGetSymbolAddress((void**)&wv,   g_wv);
    cudaGetSymbolAddress((void**)&wp,   g_wp);

    cudaFuncSetAttribute(hmma_qkv,  cudaFuncAttributeMaxDynamicSharedMemorySize, SMEM_HMMA);
    cudaFuncSetAttribute(hmma_gemm, cudaFuncAttributeMaxDynamicSharedMemorySize, SMEM_HMMA);
    cudaFuncSetAttribute(fattn,     cudaFuncAttributeMaxDynamicSharedMemorySize, SMEM_FATT);

    cudaStream_t s2 = get_side_stream();
    cudaEvent_t evPre  = get_event(0);
    cudaEvent_t evLog  = get_event(1);

    // ---- prep (main stream) ----
    dim3 wst(32, 8), wsg(32, 32, 5);
    wround_T5<<<wsg, wst>>>(Wpre, Wq, Wk, Wv, Wproj, wpre, wq, wk, wv, wp);
    const int n2 = MROWS * CC / 2;
    round2h<<<(n2 + 255) / 256, 256>>>((const float2*)x, (__half2*)x16, n2);

    // ---- pre GEMM (main stream) ----
    dim3 mb(256);
    dim3 gpre(8, MROWS / 128, 1);                 // group 0 only
    hmma_qkv<<<gpre, mb, SMEM_HMMA>>>(x16, wpre, wq, wk, wv, bpre,
                                      pre, q16, k16, v16, 0);
    cudaEventRecord(evPre, 0);

    // ---- fork: logits on side stream, q/k/v on main ----
    cudaStreamWaitEvent(s2, evPre, 0);
    dim3 glog(36, 1, BB);
    hmma_gemm<<<glog, mb, SMEM_HMMA, s2>>>(pre, pre, nullptr, nullptr,
                                           nullptr, lg, EPI_LOGITS,
                                           (long long)NN * CC, (long long)NN * CC);
    cudaEventRecord(evLog, s2);

    dim3 gqkv(24, MROWS / 128, 1);                // groups 1..3
    hmma_qkv<<<gqkv, mb, SMEM_HMMA>>>(x16, wpre, wq, wk, wv, bpre,
                                      pre, q16, k16, v16, 1);

    // ---- join, then attention ----
    cudaStreamWaitEvent(0, evLog, 0);
    dim3 ga(NN / 128, BB * HH);
    fattn<<<ga, 256, SMEM_FATT>>>(q16, k16, v16, lg, pi, ctx);

    // ---- projection + residual ----
    dim3 gl(CC / 128, MROWS / 128, 1);
    hmma_gemm<<<gl, mb, SMEM_HMMA>>>(ctx, wp, bproj, x,
                                     out, nullptr, EPI_RESID, 0, 0);
}